// round 7
// baseline (speedup 1.0000x reference)
#include <cuda_runtime.h>
#include <cstdint>

#define BB 8
#define CIN 128
#define COUT 128
#define HH 64
#define WW 64
#define KK 16
#define HO 61
#define WO 61
#define NPIX (HO * WO)        // 3721
#define MT 128                // M tile
#define MTILES 30
#define NCHUNK 64             // K chunks of 32

#define ALD 36                // As row stride in words ([m][k] layout, 32 k + 4 pad)
#define AS_BUF (128 * ALD)    // floats per A buffer (18432 B)

// ---- smem layout (bytes)
#define SM_AS    0                         // 2 x 18432 = 36864
#define SM_BS    36864                     // 2 x 16384 = 32768
#define SM_BIAS  (36864 + 32768)           // 512
#define SMEM_TOTAL (36864 + 32768 + 512)   // 70144

__device__ float g_inT[(size_t)BB * HH * WW * CIN];     // NHWC input, 16.8 MB
__device__ uint32_t g_wb[(size_t)NCHUNK * 4096];        // frag-packed tf32 weights, 1 MB

static __device__ __forceinline__ uint32_t f2tf32(float f) {
    uint32_t r;
    asm("cvt.rn.tf32.f32 %0, %1;" : "=r"(r) : "f"(f));
    return r;
}
static __device__ __forceinline__ uint64_t splat2(float f) {
    uint64_t r;
    asm("mov.b64 %0, {%1, %1};" : "=l"(r) : "f"(f));
    return r;
}
static __device__ __forceinline__ uint64_t mul2(uint64_t a, uint64_t b) {
    uint64_t r;
    asm("mul.rn.f32x2 %0, %1, %2;" : "=l"(r) : "l"(a), "l"(b));
    return r;
}
static __device__ __forceinline__ uint64_t fma2(uint64_t a, uint64_t b, uint64_t c) {
    uint64_t r;
    asm("fma.rn.f32x2 %0, %1, %2, %3;" : "=l"(r) : "l"(a), "l"(b), "l"(c));
    return r;
}
static __device__ __forceinline__ void unpk(float& lo, float& hi, uint64_t v) {
    asm("mov.b64 {%0, %1}, %2;" : "=f"(lo), "=f"(hi) : "l"(v));
}
static __device__ __forceinline__ void mma8(float* d, const uint32_t* a, const uint32_t* b) {
    asm volatile(
        "mma.sync.aligned.m16n8k8.row.col.f32.tf32.tf32.f32 "
        "{%0,%1,%2,%3}, {%4,%5,%6,%7}, {%8,%9}, {%0,%1,%2,%3};"
        : "+f"(d[0]), "+f"(d[1]), "+f"(d[2]), "+f"(d[3])
        : "r"(a[0]), "r"(a[1]), "r"(a[2]), "r"(a[3]), "r"(b[0]), "r"(b[1]));
}
static __device__ __forceinline__ void cp16(uint32_t dst, const void* src) {
    asm volatile("cp.async.cg.shared.global [%0], [%1], 16;" :: "r"(dst), "l"(src));
}
static __device__ __forceinline__ void cp_commit() {
    asm volatile("cp.async.commit_group;" ::: "memory");
}
static __device__ __forceinline__ void cp_wait0() {
    asm volatile("cp.async.wait_group 0;" ::: "memory");
}

// ---------------------------------------------------------------------------
// Kernel 1: NCHW -> NHWC transpose, float4 both directions
// ---------------------------------------------------------------------------
__global__ void transpose_kernel(const float* __restrict__ inp) {
    __shared__ float tile[WW][CIN + 4];
    int by = blockIdx.x;
    int b = by / HH, y = by % HH;
    const float* src = inp + (size_t)b * CIN * HH * WW + (size_t)y * WW;
#pragma unroll
    for (int it = 0; it < 8; ++it) {
        int i = threadIdx.x + it * 256;          // i < 2048
        int c = i >> 4, xq = i & 15;
        float4 v = ((const float4*)(src + (size_t)c * HH * WW))[xq];
        tile[xq * 4 + 0][c] = v.x;
        tile[xq * 4 + 1][c] = v.y;
        tile[xq * 4 + 2][c] = v.z;
        tile[xq * 4 + 3][c] = v.w;
    }
    __syncthreads();
    float4* dst = (float4*)(g_inT + ((size_t)b * HH + y) * WW * CIN);
#pragma unroll
    for (int it = 0; it < 8; ++it) {
        int i = threadIdx.x + it * 256;
        int x = i >> 5, cq = i & 31;
        float4 v = *(const float4*)&tile[x][cq * 4];
        dst[x * (CIN / 4) + cq] = v;
    }
}

// ---------------------------------------------------------------------------
// Kernel 2: weight flip + tf32 + pack in mma B-fragment order.
// ---------------------------------------------------------------------------
__global__ void wpack_kernel(const float* __restrict__ wgt) {
    int idx = blockIdx.x * blockDim.x + threadIdx.x;
    if (idx >= NCHUNK * 4096) return;
    int pair = idx & 1;
    int lane = (idx >> 1) & 31;
    int na   = (idx >> 6) & 15;
    int s    = (idx >> 10) & 3;
    int t    = idx >> 12;
    int n = na * 8 + (lane >> 2);
    int kc = s * 8 + (lane & 3) + pair * 4;
    int c = (t & 3) * 32 + kc;
    int dk = t >> 2;
    int ki = dk >> 2, kj = dk & 3;
    float v = wgt[(((size_t)n * CIN + c) * 4 + (3 - ki)) * 4 + (3 - kj)];
    g_wb[idx] = f2tf32(v);
}

// ---------------------------------------------------------------------------
// Kernel 3: fused bilinear sample + tf32 mma GEMM, double-buffered pipeline.
// ---------------------------------------------------------------------------
__global__ void __launch_bounds__(256, 2)
main_kernel(const float* __restrict__ offset, const float* __restrict__ mask,
            const float* __restrict__ bias, float* __restrict__ out) {
    extern __shared__ char smem[];
    float* As = (float*)(smem + SM_AS);       // [2][128][ALD]
    float* Bs = (float*)(smem + SM_BS);       // [2][4096]
    float* bias_s = (float*)(smem + SM_BIAS);

    const int tid = threadIdx.x;
    const int mtile = blockIdx.x;
    const int b = blockIdx.y;
    const int lane = tid & 31;
    const int wid = tid >> 5;
    const int mw = wid & 3, nw = wid >> 2;

    if (tid < COUT) bias_s[tid] = bias[tid];

    const int px = tid >> 1;
    const int h = tid & 1;
    const int p = mtile * MT + px;
    const bool pvalid = p < NPIX;
    const int oh = pvalid ? p / WO : 0;
    const int ow = pvalid ? p % WO : 0;
    const float* inTb = g_inT + (size_t)b * HH * WW * CIN;

    float acc[2][8][4];
#pragma unroll
    for (int i = 0; i < 2; ++i)
#pragma unroll
        for (int j = 0; j < 8; ++j)
#pragma unroll
            for (int e = 0; e < 4; ++e) acc[i][j][e] = 0.f;

    uint64_t u00 = 0, u01 = 0, u10 = 0, u11 = 0;   // packed f32x2 bilinear weights
    int4 bv = {0, 0, 0, 0};
    float pdy = 0.f, pdx = 0.f, pmk = 0.f;

    auto calc_params = [&](int dk, float dy, float dx, float mk) {
        float w00 = 0.f, w01 = 0.f, w10 = 0.f, w11 = 0.f;
        bv = make_int4(0, 0, 0, 0);
        if (pvalid) {
            int ki = dk >> 2, kj = dk & 3;
            float y = dy + (float)(ki + oh);
            float x = dx + (float)(kj + ow);
            float y0f = floorf(y), x0f = floorf(x);
            int y0 = (int)y0f, x0 = (int)x0f;
            float wy = y - y0f, wx = x - x0f;
            float a00 = (1.f - wy) * (1.f - wx) * mk;
            float a01 = (1.f - wy) * wx * mk;
            float a10 = wy * (1.f - wx) * mk;
            float a11 = wy * wx * mk;
            bool vy0 = (y0 >= 0) && (y0 < HH);
            bool vy1 = (y0 + 1 >= 0) && (y0 + 1 < HH);
            bool vx0 = (x0 >= 0) && (x0 < WW);
            bool vx1 = (x0 + 1 >= 0) && (x0 + 1 < WW);
            w00 = (vy0 && vx0) ? a00 : 0.f;
            w01 = (vy0 && vx1) ? a01 : 0.f;
            w10 = (vy1 && vx0) ? a10 : 0.f;
            w11 = (vy1 && vx1) ? a11 : 0.f;
            int y0c = min(max(y0, 0), HH - 1), y1c = min(max(y0 + 1, 0), HH - 1);
            int x0c = min(max(x0, 0), WW - 1), x1c = min(max(x0 + 1, 0), WW - 1);
            bv.x = (y0c * WW + x0c) * CIN;
            bv.y = (y0c * WW + x1c) * CIN;
            bv.z = (y1c * WW + x0c) * CIN;
            bv.w = (y1c * WW + x1c) * CIN;
        }
        u00 = splat2(w00); u01 = splat2(w01); u10 = splat2(w10); u11 = splat2(w11);
    };
    auto prefetch_om = [&](int dk) {
        if (pvalid && dk < KK) {
            size_t ob = (((size_t)b * 2 * KK + 2 * dk) * HO + oh) * WO + ow;
            pdy = offset[ob];
            pdx = offset[ob + (size_t)HO * WO];
            pmk = mask[(((size_t)b * KK + dk) * HO + oh) * WO + ow];
        }
    };
    // interp one 4-channel group (packed f32x2) and store as STS.128
    auto interp_store = [&](float* An, int s, const ulonglong2& g0, const ulonglong2& g1,
                            const ulonglong2& g2, const ulonglong2& g3) {
        uint64_t lo = mul2(u00, g0.x);
        lo = fma2(u01, g1.x, lo);
        lo = fma2(u10, g2.x, lo);
        lo = fma2(u11, g3.x, lo);
        uint64_t hi = mul2(u00, g0.y);
        hi = fma2(u01, g1.y, hi);
        hi = fma2(u10, g2.y, hi);
        hi = fma2(u11, g3.y, hi);
        float f0, f1, f2, f3;
        unpk(f0, f1, lo);
        unpk(f2, f3, hi);
        uint4 r = make_uint4(f2tf32(f0), f2tf32(f1), f2tf32(f2), f2tf32(f3));
        *(uint4*)&An[px * ALD + h * 16 + s * 4] = r;
    };

    // ---- prologue: params dk0, prefetch dk1, fill chunk 0 into buffer 0 ----
    {
        float dy0 = 0.f, dx0 = 0.f, mk0 = 0.f;
        if (pvalid) {
            size_t ob = (((size_t)b * 2 * KK) * HO + oh) * WO + ow;
            dy0 = offset[ob];
            dx0 = offset[ob + (size_t)HO * WO];
            mk0 = mask[(((size_t)b * KK) * HO + oh) * WO + ow];
        }
        calc_params(0, dy0, dx0, mk0);
        prefetch_om(1);
        {
            const float4* src = (const float4*)g_wb;
            uint32_t d0 = (uint32_t)__cvta_generic_to_shared(Bs);
#pragma unroll
            for (int j = 0; j < 4; ++j)
                cp16(d0 + (uint32_t)(tid + j * 256) * 16, src + tid + j * 256);
            cp_commit();
        }
        const int c0 = h * 16;
#pragma unroll
        for (int s = 0; s < 4; ++s) {
            ulonglong2 g0 = *(const ulonglong2*)(inTb + bv.x + c0 + s * 4);
            ulonglong2 g1 = *(const ulonglong2*)(inTb + bv.y + c0 + s * 4);
            ulonglong2 g2 = *(const ulonglong2*)(inTb + bv.z + c0 + s * 4);
            ulonglong2 g3 = *(const ulonglong2*)(inTb + bv.w + c0 + s * 4);
            interp_store(As, s, g0, g1, g2, g3);
        }
        cp_wait0();
        __syncthreads();
    }

    // ---- main loop ----
    for (int t = 0; t < NCHUNK; ++t) {
        const int cur = t & 1;
        const uint32_t* Acu = (const uint32_t*)(As + cur * AS_BUF);
        const uint32_t* Bcu = (const uint32_t*)(Bs + cur * 4096);
        float* An = As + (cur ^ 1) * AS_BUF;
        const bool hn = (t < NCHUNK - 1);

        int c0n = 0;
        ulonglong2 g0, g1, g2, g3;
        if (hn) {
            if (((t + 1) & 3) == 0) {
                int dkn = (t + 1) >> 2;
                calc_params(dkn, pdy, pdx, pmk);
                prefetch_om(dkn + 1);
            }
            const float4* src = (const float4*)(g_wb + (size_t)(t + 1) * 4096);
            uint32_t d0 = (uint32_t)__cvta_generic_to_shared(Bs + (cur ^ 1) * 4096);
#pragma unroll
            for (int j = 0; j < 4; ++j)
                cp16(d0 + (uint32_t)(tid + j * 256) * 16, src + tid + j * 256);
            cp_commit();
            c0n = ((t + 1) & 3) * 32 + h * 16;
            // gather group 0 (covered by s=0 mma phase)
            g0 = *(const ulonglong2*)(inTb + bv.x + c0n);
            g1 = *(const ulonglong2*)(inTb + bv.y + c0n);
            g2 = *(const ulonglong2*)(inTb + bv.z + c0n);
            g3 = *(const ulonglong2*)(inTb + bv.w + c0n);
        }

#pragma unroll
        for (int s = 0; s < 4; ++s) {
            // B fragments (LDS.64, conflict-free)
            uint32_t bf[8][2];
#pragma unroll
            for (int na = 0; na < 8; ++na) {
                uint2 v = *(const uint2*)&Bcu[((s * 16 + nw * 8 + na) * 32 + lane) * 2];
                bf[na][0] = v.x; bf[na][1] = v.y;
            }
            // A fragments ([m][k] layout, conflict-free LDS.32)
            uint32_t af[2][4];
            {
                const int k0 = s * 8 + (lane & 3);
#pragma unroll
                for (int ma = 0; ma < 2; ++ma) {
                    const int m = (mw * 2 + ma) * 16 + (lane >> 2);
                    af[ma][0] = Acu[m * ALD + k0];
                    af[ma][1] = Acu[(m + 8) * ALD + k0];
                    af[ma][2] = Acu[m * ALD + k0 + 4];
                    af[ma][3] = Acu[(m + 8) * ALD + k0 + 4];
                }
            }
            // interp + store group s (loaded one phase earlier)
            if (hn) interp_store(An, s, g0, g1, g2, g3);
            // prefetch gather group s+1 (consumed next iteration)
            if (hn && s < 3) {
                g0 = *(const ulonglong2*)(inTb + bv.x + c0n + (s + 1) * 4);
                g1 = *(const ulonglong2*)(inTb + bv.y + c0n + (s + 1) * 4);
                g2 = *(const ulonglong2*)(inTb + bv.z + c0n + (s + 1) * 4);
                g3 = *(const ulonglong2*)(inTb + bv.w + c0n + (s + 1) * 4);
            }
            // MMA
#pragma unroll
            for (int ma = 0; ma < 2; ++ma)
#pragma unroll
                for (int na = 0; na < 8; ++na)
                    mma8(acc[ma][na], af[ma], bf[na]);
        }
        cp_wait0();
        __syncthreads();
    }

    // ---- epilogue: stage through smem for coalesced NCHW writes ----
    float* Cs = (float*)smem;   // 64 n x 128 m = 32 KB
    float* ob = out + (size_t)b * COUT * NPIX;
#pragma unroll 1
    for (int nhalf = 0; nhalf < 2; ++nhalf) {
        if (nw == nhalf) {
#pragma unroll
            for (int ma = 0; ma < 2; ++ma)
#pragma unroll
                for (int na = 0; na < 8; ++na)
#pragma unroll
                    for (int d = 0; d < 4; ++d) {
                        int nl = na * 8 + (lane & 3) * 2 + (d & 1);
                        int m = (mw * 2 + ma) * 16 + (lane >> 2) + 8 * (d >> 1);
                        Cs[nl * 128 + m] = acc[ma][na][d];
                    }
        }
        __syncthreads();
#pragma unroll
        for (int it = 0; it < 32; ++it) {
            int idx = tid + it * 256;
            int nl = idx >> 7, m = idx & 127;
            int pp = mtile * MT + m;
            int n = nhalf * 64 + nl;
            if (pp < NPIX)
                ob[(size_t)n * NPIX + pp] = Cs[idx] + bias_s[n];
        }
        __syncthreads();
    }
}

// ---------------------------------------------------------------------------
extern "C" void kernel_launch(void* const* d_in, const int* in_sizes, int n_in,
                              void* d_out, int out_size) {
    const float* inp    = (const float*)d_in[0];
    const float* offset = (const float*)d_in[1];
    const float* mask   = (const float*)d_in[2];
    const float* weight = (const float*)d_in[3];
    const float* bias   = (const float*)d_in[4];
    float* out = (float*)d_out;

    cudaFuncSetAttribute(main_kernel, cudaFuncAttributeMaxDynamicSharedMemorySize,
                         SMEM_TOTAL);

    transpose_kernel<<<BB * HH, 256>>>(inp);
    wpack_kernel<<<(NCHUNK * 4096 + 255) / 256, 256>>>(weight);
    main_kernel<<<dim3(MTILES, BB), 256, SMEM_TOTAL>>>(offset, mask, bias, out);
}

// round 8
// speedup vs baseline: 1.1175x; 1.1175x over previous
#include <cuda_runtime.h>
#include <cuda_fp16.h>
#include <cstdint>

#define BB 8
#define CIN 128
#define COUT 128
#define HH 64
#define WW 64
#define KK 16
#define HO 61
#define WO 61
#define NPIX (HO * WO)        // 3721
#define MT 128                // M tile
#define MTILES 30
#define NCHUNK 64             // K chunks of 32

#define SLD 136               // As row stride (floats): bank-bijective
#define AS_BUF (32 * SLD)     // floats per A buffer

// ---- smem layout (bytes)
#define SM_AS    0                        // 2 x 17408 = 34816
#define SM_BS    34816                    // 2 x 16384 = 32768
#define SM_BIAS  (34816 + 32768)          // 512
#define SMEM_TOTAL (34816 + 32768 + 512)  // 68096

// Scratch (allocation-free: __device__ globals)
__device__ __half g_inT[(size_t)BB * HH * WW * CIN];    // NHWC input, fp16, 8.4 MB
__device__ uint32_t g_wb[(size_t)NCHUNK * 4096];        // frag-packed tf32 weights, 1 MB

static __device__ __forceinline__ uint32_t f2tf32(float f) {
    uint32_t r;
    asm("cvt.rn.tf32.f32 %0, %1;" : "=r"(r) : "f"(f));
    return r;
}
static __device__ __forceinline__ void mma8(float* d, const uint32_t* a, const uint32_t* b) {
    asm volatile(
        "mma.sync.aligned.m16n8k8.row.col.f32.tf32.tf32.f32 "
        "{%0,%1,%2,%3}, {%4,%5,%6,%7}, {%8,%9}, {%0,%1,%2,%3};"
        : "+f"(d[0]), "+f"(d[1]), "+f"(d[2]), "+f"(d[3])
        : "r"(a[0]), "r"(a[1]), "r"(a[2]), "r"(a[3]), "r"(b[0]), "r"(b[1]));
}
static __device__ __forceinline__ void cp16(uint32_t dst, const void* src) {
    asm volatile("cp.async.cg.shared.global [%0], [%1], 16;" :: "r"(dst), "l"(src));
}
static __device__ __forceinline__ void cp_commit() {
    asm volatile("cp.async.commit_group;" ::: "memory");
}
static __device__ __forceinline__ void cp_wait0() {
    asm volatile("cp.async.wait_group 0;" ::: "memory");
}

// ---------------------------------------------------------------------------
// Kernel 1: NCHW fp32 -> NHWC fp16 transpose
// ---------------------------------------------------------------------------
__global__ void transpose_kernel(const float* __restrict__ inp) {
    __shared__ float tile[CIN][WW + 1];
    int by = blockIdx.x;
    int b = by / HH, y = by % HH;
    const float* src = inp + (size_t)b * CIN * HH * WW + (size_t)y * WW;
    for (int i = threadIdx.x; i < CIN * WW; i += blockDim.x) {
        int c = i / WW, x = i % WW;
        tile[c][x] = src[(size_t)c * HH * WW + x];
    }
    __syncthreads();
    __half* dst = g_inT + ((size_t)b * HH + y) * WW * CIN;
    for (int i = threadIdx.x; i < CIN * WW; i += blockDim.x) {
        int x = i / CIN, c = i % CIN;
        dst[(size_t)x * CIN + c] = __float2half(tile[c][x]);
    }
}

// ---------------------------------------------------------------------------
// Kernel 2: weight flip + tf32 + pack in mma B-fragment order.
// ---------------------------------------------------------------------------
__global__ void wpack_kernel(const float* __restrict__ wgt) {
    int idx = blockIdx.x * blockDim.x + threadIdx.x;
    if (idx >= NCHUNK * 4096) return;
    int pair = idx & 1;
    int lane = (idx >> 1) & 31;
    int na   = (idx >> 6) & 15;
    int s    = (idx >> 10) & 3;
    int t    = idx >> 12;
    int n = na * 8 + (lane >> 2);
    int kc = s * 8 + (lane & 3) + pair * 4;
    int c = (t & 3) * 32 + kc;
    int dk = t >> 2;
    int ki = dk >> 2, kj = dk & 3;
    float v = wgt[(((size_t)n * CIN + c) * 4 + (3 - ki)) * 4 + (3 - kj)];
    g_wb[idx] = f2tf32(v);
}

// ---------------------------------------------------------------------------
// Kernel 3: fused bilinear sample (fp16 src) + tf32 mma GEMM, double-buffered.
// ---------------------------------------------------------------------------
__global__ void __launch_bounds__(256, 2)
main_kernel(const float* __restrict__ offset, const float* __restrict__ mask,
            const float* __restrict__ bias, float* __restrict__ out) {
    extern __shared__ char smem[];
    float* As = (float*)(smem + SM_AS);       // [2][32][SLD]
    float* Bs = (float*)(smem + SM_BS);       // [2][4096]
    float* bias_s = (float*)(smem + SM_BIAS);

    const int tid = threadIdx.x;
    const int mtile = blockIdx.x;
    const int b = blockIdx.y;
    const int lane = tid & 31;
    const int wid = tid >> 5;
    const int mw = wid & 3, nw = wid >> 2;

    if (tid < COUT) bias_s[tid] = bias[tid];

    // fill-thread mapping: 2 threads per pixel, 16 channels each
    const int px = tid >> 1;
    const int h = tid & 1;
    const int p = mtile * MT + px;
    const bool pvalid = p < NPIX;
    const int oh = pvalid ? p / WO : 0;
    const int ow = pvalid ? p % WO : 0;
    const __half* inTb = g_inT + (size_t)b * HH * WW * CIN;

    float acc[2][8][4];
#pragma unroll
    for (int i = 0; i < 2; ++i)
#pragma unroll
        for (int j = 0; j < 8; ++j)
#pragma unroll
            for (int e = 0; e < 4; ++e) acc[i][j][e] = 0.f;

    float4 wv = {0.f, 0.f, 0.f, 0.f};
    int4 bv = {0, 0, 0, 0};
    float pdy = 0.f, pdx = 0.f, pmk = 0.f;

    auto calc_params = [&](int dk, float dy, float dx, float mk) {
        wv = make_float4(0.f, 0.f, 0.f, 0.f);
        bv = make_int4(0, 0, 0, 0);
        if (pvalid) {
            int ki = dk >> 2, kj = dk & 3;
            float y = dy + (float)(ki + oh);
            float x = dx + (float)(kj + ow);
            float y0f = floorf(y), x0f = floorf(x);
            int y0 = (int)y0f, x0 = (int)x0f;
            float wy = y - y0f, wx = x - x0f;
            float w00 = (1.f - wy) * (1.f - wx) * mk;
            float w01 = (1.f - wy) * wx * mk;
            float w10 = wy * (1.f - wx) * mk;
            float w11 = wy * wx * mk;
            bool vy0 = (y0 >= 0) && (y0 < HH);
            bool vy1 = (y0 + 1 >= 0) && (y0 + 1 < HH);
            bool vx0 = (x0 >= 0) && (x0 < WW);
            bool vx1 = (x0 + 1 >= 0) && (x0 + 1 < WW);
            wv.x = (vy0 && vx0) ? w00 : 0.f;
            wv.y = (vy0 && vx1) ? w01 : 0.f;
            wv.z = (vy1 && vx0) ? w10 : 0.f;
            wv.w = (vy1 && vx1) ? w11 : 0.f;
            int y0c = min(max(y0, 0), HH - 1), y1c = min(max(y0 + 1, 0), HH - 1);
            int x0c = min(max(x0, 0), WW - 1), x1c = min(max(x0 + 1, 0), WW - 1);
            bv.x = (y0c * WW + x0c) * CIN;
            bv.y = (y0c * WW + x1c) * CIN;
            bv.z = (y1c * WW + x0c) * CIN;
            bv.w = (y1c * WW + x1c) * CIN;
        }
    };
    auto prefetch_om = [&](int dk) {
        if (pvalid && dk < KK) {
            size_t ob = (((size_t)b * 2 * KK + 2 * dk) * HO + oh) * WO + ow;
            pdy = offset[ob];
            pdx = offset[ob + (size_t)HO * WO];
            pmk = mask[(((size_t)b * KK + dk) * HO + oh) * WO + ow];
        }
    };
    // interp one 4-channel group from fp16 corner data, store tf32 to smem
    auto interp_store = [&](float* An, int s, uint2 ga, uint2 gb, uint2 gc, uint2 gd) {
        float2 a0 = __half22float2(*(__half2*)&ga.x), a1 = __half22float2(*(__half2*)&ga.y);
        float2 b0 = __half22float2(*(__half2*)&gb.x), b1 = __half22float2(*(__half2*)&gb.y);
        float2 c0 = __half22float2(*(__half2*)&gc.x), c1 = __half22float2(*(__half2*)&gc.y);
        float2 d0 = __half22float2(*(__half2*)&gd.x), d1 = __half22float2(*(__half2*)&gd.y);
        float vs[4];
        vs[0] = wv.x * a0.x + wv.y * b0.x + wv.z * c0.x + wv.w * d0.x;
        vs[1] = wv.x * a0.y + wv.y * b0.y + wv.z * c0.y + wv.w * d0.y;
        vs[2] = wv.x * a1.x + wv.y * b1.x + wv.z * c1.x + wv.w * d1.x;
        vs[3] = wv.x * a1.y + wv.y * b1.y + wv.z * c1.y + wv.w * d1.y;
#pragma unroll
        for (int e = 0; e < 4; ++e)
            An[(h * 16 + s * 4 + e) * SLD + px] = __uint_as_float(f2tf32(vs[e]));
    };

    // ---- prologue: params dk0, prefetch dk1, fill chunk 0 into buffer 0 ----
    {
        float dy0 = 0.f, dx0 = 0.f, mk0 = 0.f;
        if (pvalid) {
            size_t ob = (((size_t)b * 2 * KK) * HO + oh) * WO + ow;
            dy0 = offset[ob];
            dx0 = offset[ob + (size_t)HO * WO];
            mk0 = mask[(((size_t)b * KK) * HO + oh) * WO + ow];
        }
        calc_params(0, dy0, dx0, mk0);
        prefetch_om(1);
        {
            const float4* src = (const float4*)g_wb;
            uint32_t d0 = (uint32_t)__cvta_generic_to_shared(Bs);
#pragma unroll
            for (int j = 0; j < 4; ++j)
                cp16(d0 + (uint32_t)(tid + j * 256) * 16, src + tid + j * 256);
            cp_commit();
        }
        const int c0 = h * 16;
#pragma unroll
        for (int s = 0; s < 4; ++s) {
            uint2 ga = *(const uint2*)(inTb + bv.x + c0 + s * 4);
            uint2 gb = *(const uint2*)(inTb + bv.y + c0 + s * 4);
            uint2 gc = *(const uint2*)(inTb + bv.z + c0 + s * 4);
            uint2 gd = *(const uint2*)(inTb + bv.w + c0 + s * 4);
            interp_store(As, s, ga, gb, gc, gd);
        }
        cp_wait0();
        __syncthreads();
    }

    // ---- main loop ----
    for (int t = 0; t < NCHUNK; ++t) {
        const int cur = t & 1;
        const uint32_t* Acu = (const uint32_t*)(As + cur * AS_BUF);
        const uint32_t* Bcu = (const uint32_t*)(Bs + cur * 4096);
        float* An = As + (cur ^ 1) * AS_BUF;
        const bool hn = (t < NCHUNK - 1);

        int c0n = 0;
        uint2 ga, gb, gc, gd;
        if (hn) {
            if (((t + 1) & 3) == 0) {
                int dkn = (t + 1) >> 2;
                calc_params(dkn, pdy, pdx, pmk);
                prefetch_om(dkn + 1);
            }
            const float4* src = (const float4*)(g_wb + (size_t)(t + 1) * 4096);
            uint32_t d0 = (uint32_t)__cvta_generic_to_shared(Bs + (cur ^ 1) * 4096);
#pragma unroll
            for (int j = 0; j < 4; ++j)
                cp16(d0 + (uint32_t)(tid + j * 256) * 16, src + tid + j * 256);
            cp_commit();
            c0n = ((t + 1) & 3) * 32 + h * 16;
            ga = *(const uint2*)(inTb + bv.x + c0n);
            gb = *(const uint2*)(inTb + bv.y + c0n);
            gc = *(const uint2*)(inTb + bv.z + c0n);
            gd = *(const uint2*)(inTb + bv.w + c0n);
        }

#pragma unroll
        for (int s = 0; s < 4; ++s) {
            // A fragments (conflict-free LDS.32, [k][m] layout)
            uint32_t af[2][4];
            {
                const int k0 = s * 8 + (lane & 3);
                const int mbase = mw * 32 + (lane >> 2);
#pragma unroll
                for (int ma = 0; ma < 2; ++ma) {
                    const int m = mbase + ma * 16;
                    af[ma][0] = Acu[k0 * SLD + m];
                    af[ma][1] = Acu[k0 * SLD + m + 8];
                    af[ma][2] = Acu[(k0 + 4) * SLD + m];
                    af[ma][3] = Acu[(k0 + 4) * SLD + m + 8];
                }
            }
            // B fragments
            uint32_t bf[8][2];
#pragma unroll
            for (int na = 0; na < 8; ++na) {
                uint2 v = *(const uint2*)&Bcu[((s * 16 + nw * 8 + na) * 32 + lane) * 2];
                bf[na][0] = v.x; bf[na][1] = v.y;
            }
            // MMA
#pragma unroll
            for (int ma = 0; ma < 2; ++ma)
#pragma unroll
                for (int na = 0; na < 8; ++na)
                    mma8(acc[ma][na], af[ma], bf[na]);

            // consume gather group s -> store into next A buffer, issue group s+1
            if (hn) {
                interp_store(An, s, ga, gb, gc, gd);
                if (s < 3) {
                    ga = *(const uint2*)(inTb + bv.x + c0n + (s + 1) * 4);
                    gb = *(const uint2*)(inTb + bv.y + c0n + (s + 1) * 4);
                    gc = *(const uint2*)(inTb + bv.z + c0n + (s + 1) * 4);
                    gd = *(const uint2*)(inTb + bv.w + c0n + (s + 1) * 4);
                }
            }
        }
        cp_wait0();
        __syncthreads();
    }

    // ---- epilogue: stage through smem for coalesced NCHW writes ----
    float* Cs = (float*)smem;   // 64 n x 128 m = 32 KB
    float* ob = out + (size_t)b * COUT * NPIX;
#pragma unroll 1
    for (int nhalf = 0; nhalf < 2; ++nhalf) {
        if (nw == nhalf) {
#pragma unroll
            for (int ma = 0; ma < 2; ++ma)
#pragma unroll
                for (int na = 0; na < 8; ++na)
#pragma unroll
                    for (int d = 0; d < 4; ++d) {
                        int nl = na * 8 + (lane & 3) * 2 + (d & 1);
                        int m = (mw * 2 + ma) * 16 + (lane >> 2) + 8 * (d >> 1);
                        Cs[nl * 128 + m] = acc[ma][na][d];
                    }
        }
        __syncthreads();
#pragma unroll
        for (int it = 0; it < 32; ++it) {
            int idx = tid + it * 256;
            int nl = idx >> 7, m = idx & 127;
            int pp = mtile * MT + m;
            int n = nhalf * 64 + nl;
            if (pp < NPIX)
                ob[(size_t)n * NPIX + pp] = Cs[idx] + bias_s[n];
        }
        __syncthreads();
    }
}

// ---------------------------------------------------------------------------
extern "C" void kernel_launch(void* const* d_in, const int* in_sizes, int n_in,
                              void* d_out, int out_size) {
    const float* inp    = (const float*)d_in[0];
    const float* offset = (const float*)d_in[1];
    const float* mask   = (const float*)d_in[2];
    const float* weight = (const float*)d_in[3];
    const float* bias   = (const float*)d_in[4];
    float* out = (float*)d_out;

    cudaFuncSetAttribute(main_kernel, cudaFuncAttributeMaxDynamicSharedMemorySize,
                         SMEM_TOTAL);

    transpose_kernel<<<BB * HH, 256>>>(inp);
    wpack_kernel<<<(NCHUNK * 4096 + 255) / 256, 256>>>(weight);
    main_kernel<<<dim3(MTILES, BB), 256, SMEM_TOTAL>>>(offset, mask, bias, out);
}

// round 9
// speedup vs baseline: 1.8861x; 1.6878x over previous
#include <cuda_runtime.h>
#include <cuda_fp16.h>
#include <cstdint>

#define BB 8
#define CIN 128
#define COUT 128
#define HH 64
#define WW 64
#define KK 16
#define HO 61
#define WO 61
#define NPIX (HO * WO)        // 3721
#define MT 128
#define MTILES 30
#define NCHUNK 64             // K chunks of 32

#define SLD 136               // As row stride in words (half2 units per k2-row)
#define AS_BUF (16 * SLD)     // words per A buffer (16 k2-rows) = 8704 B

// ---- smem layout (bytes)
#define SM_AS    0                        // 2 x 8704 = 17408
#define SM_BS    17408                    // 2 x 8192 = 16384
#define SM_BIAS  (17408 + 16384)          // 512
#define SMEM_TOTAL (17408 + 16384 + 512)  // 34304

// Scratch (allocation-free: __device__ globals)
__device__ __half g_inT[(size_t)BB * HH * WW * CIN];    // NHWC input, fp16, 8.4 MB
__device__ uint32_t g_wb[(size_t)NCHUNK * 2048];        // frag-packed fp16 weights, 512 KB

static __device__ __forceinline__ void mma16(float* d, const uint32_t* a, const uint32_t* b) {
    asm volatile(
        "mma.sync.aligned.m16n8k16.row.col.f32.f16.f16.f32 "
        "{%0,%1,%2,%3}, {%4,%5,%6,%7}, {%8,%9}, {%0,%1,%2,%3};"
        : "+f"(d[0]), "+f"(d[1]), "+f"(d[2]), "+f"(d[3])
        : "r"(a[0]), "r"(a[1]), "r"(a[2]), "r"(a[3]), "r"(b[0]), "r"(b[1]));
}
static __device__ __forceinline__ void cp16(uint32_t dst, const void* src) {
    asm volatile("cp.async.cg.shared.global [%0], [%1], 16;" :: "r"(dst), "l"(src));
}
static __device__ __forceinline__ void cp_commit() {
    asm volatile("cp.async.commit_group;" ::: "memory");
}
static __device__ __forceinline__ void cp_wait0() {
    asm volatile("cp.async.wait_group 0;" ::: "memory");
}

// ---------------------------------------------------------------------------
// Kernel 1: NCHW fp32 -> NHWC fp16 transpose
// ---------------------------------------------------------------------------
__global__ void transpose_kernel(const float* __restrict__ inp) {
    __shared__ float tile[CIN][WW + 1];
    int by = blockIdx.x;
    int b = by / HH, y = by % HH;
    const float* src = inp + (size_t)b * CIN * HH * WW + (size_t)y * WW;
    for (int i = threadIdx.x; i < CIN * WW; i += blockDim.x) {
        int c = i / WW, x = i % WW;
        tile[c][x] = src[(size_t)c * HH * WW + x];
    }
    __syncthreads();
    __half* dst = g_inT + ((size_t)b * HH + y) * WW * CIN;
    for (int i = threadIdx.x; i < CIN * WW; i += blockDim.x) {
        int x = i / CIN, c = i % CIN;
        dst[(size_t)x * CIN + c] = __float2half(tile[c][x]);
    }
}

// ---------------------------------------------------------------------------
// Kernel 2: weight flip + fp16 + pack in m16n8k16 B-fragment order.
// word idx within chunk t: ((s*16 + na)*32 + lane)*2 + r  (half2 along k)
//   n = na*8 + lane>>2 ; k_local = s*16 + (lane&3)*2 + r*8 + {0,1}
//   c = (t&3)*32 + k_local ; dk = t>>2 (spatially flipped)
// ---------------------------------------------------------------------------
__global__ void wpack_kernel(const float* __restrict__ wgt) {
    int idx = blockIdx.x * blockDim.x + threadIdx.x;
    if (idx >= NCHUNK * 2048) return;
    int r    = idx & 1;
    int lane = (idx >> 1) & 31;
    int na   = (idx >> 6) & 15;
    int s    = (idx >> 10) & 1;
    int t    = idx >> 11;
    int n = na * 8 + (lane >> 2);
    int k0 = s * 16 + (lane & 3) * 2 + r * 8;
    int dk = t >> 2;
    int ki = dk >> 2, kj = dk & 3;
    size_t base = ((size_t)n * CIN + (t & 3) * 32 + k0) * 16 + (3 - ki) * 4 + (3 - kj);
    float v0 = wgt[base];
    float v1 = wgt[base + 16];     // next c (+1) => +KH*KW elements
    __half2 h2 = __floats2half2_rn(v0, v1);
    g_wb[idx] = *(uint32_t*)&h2;
}

// ---------------------------------------------------------------------------
// Kernel 3: fused bilinear sample (fp16) + fp16 m16n8k16 mma GEMM.
// ---------------------------------------------------------------------------
__global__ void __launch_bounds__(256, 2)
main_kernel(const float* __restrict__ offset, const float* __restrict__ mask,
            const float* __restrict__ bias, float* __restrict__ out) {
    extern __shared__ char smem[];
    uint32_t* As = (uint32_t*)(smem + SM_AS);   // [2][16 k2][SLD] half2 words
    uint32_t* Bs = (uint32_t*)(smem + SM_BS);   // [2][2048]
    float* bias_s = (float*)(smem + SM_BIAS);

    const int tid = threadIdx.x;
    const int mtile = blockIdx.x;
    const int b = blockIdx.y;
    const int lane = tid & 31;
    const int wid = tid >> 5;
    const int mw = wid & 3, nw = wid >> 2;

    if (tid < COUT) bias_s[tid] = bias[tid];

    // fill-thread mapping: 2 threads per pixel, 16 channels each
    const int px = tid >> 1;
    const int h = tid & 1;
    const int p = mtile * MT + px;
    const bool pvalid = p < NPIX;
    const int oh = pvalid ? p / WO : 0;
    const int ow = pvalid ? p % WO : 0;
    const __half* inTb = g_inT + (size_t)b * HH * WW * CIN;

    float acc[2][8][4];
#pragma unroll
    for (int i = 0; i < 2; ++i)
#pragma unroll
        for (int j = 0; j < 8; ++j)
#pragma unroll
            for (int e = 0; e < 4; ++e) acc[i][j][e] = 0.f;

    float4 wv = {0.f, 0.f, 0.f, 0.f};
    int4 bv = {0, 0, 0, 0};
    float pdy = 0.f, pdx = 0.f, pmk = 0.f;

    auto calc_params = [&](int dk, float dy, float dx, float mk) {
        wv = make_float4(0.f, 0.f, 0.f, 0.f);
        bv = make_int4(0, 0, 0, 0);
        if (pvalid) {
            int ki = dk >> 2, kj = dk & 3;
            float y = dy + (float)(ki + oh);
            float x = dx + (float)(kj + ow);
            float y0f = floorf(y), x0f = floorf(x);
            int y0 = (int)y0f, x0 = (int)x0f;
            float wy = y - y0f, wx = x - x0f;
            float w00 = (1.f - wy) * (1.f - wx) * mk;
            float w01 = (1.f - wy) * wx * mk;
            float w10 = wy * (1.f - wx) * mk;
            float w11 = wy * wx * mk;
            bool vy0 = (y0 >= 0) && (y0 < HH);
            bool vy1 = (y0 + 1 >= 0) && (y0 + 1 < HH);
            bool vx0 = (x0 >= 0) && (x0 < WW);
            bool vx1 = (x0 + 1 >= 0) && (x0 + 1 < WW);
            wv.x = (vy0 && vx0) ? w00 : 0.f;
            wv.y = (vy0 && vx1) ? w01 : 0.f;
            wv.z = (vy1 && vx0) ? w10 : 0.f;
            wv.w = (vy1 && vx1) ? w11 : 0.f;
            int y0c = min(max(y0, 0), HH - 1), y1c = min(max(y0 + 1, 0), HH - 1);
            int x0c = min(max(x0, 0), WW - 1), x1c = min(max(x0 + 1, 0), WW - 1);
            bv.x = (y0c * WW + x0c) * CIN;
            bv.y = (y0c * WW + x1c) * CIN;
            bv.z = (y1c * WW + x0c) * CIN;
            bv.w = (y1c * WW + x1c) * CIN;
        }
    };
    auto prefetch_om = [&](int dk) {
        if (pvalid && dk < KK) {
            size_t ob = (((size_t)b * 2 * KK + 2 * dk) * HO + oh) * WO + ow;
            pdy = offset[ob];
            pdx = offset[ob + (size_t)HO * WO];
            pmk = mask[(((size_t)b * KK + dk) * HO + oh) * WO + ow];
        }
    };
    // interp 8 channels (one uint4 = 8 halfs per corner), store 4 half2 words
    auto interp_store = [&](uint32_t* An, int s, const uint4& ga, const uint4& gb,
                            const uint4& gc, const uint4& gd) {
        const __half2* ha = (const __half2*)&ga;
        const __half2* hb = (const __half2*)&gb;
        const __half2* hc = (const __half2*)&gc;
        const __half2* hd = (const __half2*)&gd;
#pragma unroll
        for (int w = 0; w < 4; ++w) {
            float2 a = __half22float2(ha[w]);
            float2 b2 = __half22float2(hb[w]);
            float2 c2 = __half22float2(hc[w]);
            float2 d2 = __half22float2(hd[w]);
            float lo = wv.x * a.x + wv.y * b2.x + wv.z * c2.x + wv.w * d2.x;
            float hi = wv.x * a.y + wv.y * b2.y + wv.z * c2.y + wv.w * d2.y;
            __half2 o = __floats2half2_rn(lo, hi);
            An[(h * 8 + s * 4 + w) * SLD + px] = *(uint32_t*)&o;
        }
    };

    // ---- prologue: params dk0, prefetch dk1, fill chunk 0 into buffer 0 ----
    {
        float dy0 = 0.f, dx0 = 0.f, mk0 = 0.f;
        if (pvalid) {
            size_t ob = (((size_t)b * 2 * KK) * HO + oh) * WO + ow;
            dy0 = offset[ob];
            dx0 = offset[ob + (size_t)HO * WO];
            mk0 = mask[(((size_t)b * KK) * HO + oh) * WO + ow];
        }
        calc_params(0, dy0, dx0, mk0);
        prefetch_om(1);
        {
            const float4* src = (const float4*)g_wb;
            uint32_t d0 = (uint32_t)__cvta_generic_to_shared(Bs);
#pragma unroll
            for (int j = 0; j < 2; ++j)
                cp16(d0 + (uint32_t)(tid + j * 256) * 16, src + tid + j * 256);
            cp_commit();
        }
#pragma unroll
        for (int s = 0; s < 2; ++s) {
            const int c0 = h * 16 + s * 8;
            uint4 ga = *(const uint4*)(inTb + bv.x + c0);
            uint4 gb = *(const uint4*)(inTb + bv.y + c0);
            uint4 gc = *(const uint4*)(inTb + bv.z + c0);
            uint4 gd = *(const uint4*)(inTb + bv.w + c0);
            interp_store(As, s, ga, gb, gc, gd);
        }
        cp_wait0();
        __syncthreads();
    }

    // ---- main loop ----
    for (int t = 0; t < NCHUNK; ++t) {
        const int cur = t & 1;
        const uint32_t* Acu = As + cur * AS_BUF;
        const uint32_t* Bcu = Bs + cur * 2048;
        uint32_t* An = As + (cur ^ 1) * AS_BUF;
        const bool hn = (t < NCHUNK - 1);

        int c0n = 0;
        uint4 ga, gb, gc, gd;
        if (hn) {
            if (((t + 1) & 3) == 0) {
                int dkn = (t + 1) >> 2;
                calc_params(dkn, pdy, pdx, pmk);
                prefetch_om(dkn + 1);
            }
            const float4* src = (const float4*)(g_wb + (size_t)(t + 1) * 2048);
            uint32_t d0 = (uint32_t)__cvta_generic_to_shared(Bs + (cur ^ 1) * 2048);
#pragma unroll
            for (int j = 0; j < 2; ++j)
                cp16(d0 + (uint32_t)(tid + j * 256) * 16, src + tid + j * 256);
            cp_commit();
            c0n = ((t + 1) & 3) * 32 + h * 16;
            ga = *(const uint4*)(inTb + bv.x + c0n);
            gb = *(const uint4*)(inTb + bv.y + c0n);
            gc = *(const uint4*)(inTb + bv.z + c0n);
            gd = *(const uint4*)(inTb + bv.w + c0n);
        }

#pragma unroll
        for (int s = 0; s < 2; ++s) {
            // A fragments (conflict-free LDS.32): a0,a1 at k2=s*8+(lane&3); a2,a3 at +4
            uint32_t af[2][4];
            {
                const int k2 = s * 8 + (lane & 3);
                const int mbase = mw * 32 + (lane >> 2);
#pragma unroll
                for (int ma = 0; ma < 2; ++ma) {
                    const int m = mbase + ma * 16;
                    af[ma][0] = Acu[k2 * SLD + m];
                    af[ma][1] = Acu[k2 * SLD + m + 8];
                    af[ma][2] = Acu[(k2 + 4) * SLD + m];
                    af[ma][3] = Acu[(k2 + 4) * SLD + m + 8];
                }
            }
            // B fragments (LDS.64, frag-ordered)
            uint32_t bf[8][2];
#pragma unroll
            for (int na = 0; na < 8; ++na) {
                uint2 v = *(const uint2*)&Bcu[((s * 16 + nw * 8 + na) * 32 + lane) * 2];
                bf[na][0] = v.x; bf[na][1] = v.y;
            }
            // MMA
#pragma unroll
            for (int ma = 0; ma < 2; ++ma)
#pragma unroll
                for (int na = 0; na < 8; ++na)
                    mma16(acc[ma][na], af[ma], bf[na]);

            // consume gather group s -> store into next A buffer, issue group s+1
            if (hn) {
                interp_store(An, s, ga, gb, gc, gd);
                if (s == 0) {
                    ga = *(const uint4*)(inTb + bv.x + c0n + 8);
                    gb = *(const uint4*)(inTb + bv.y + c0n + 8);
                    gc = *(const uint4*)(inTb + bv.z + c0n + 8);
                    gd = *(const uint4*)(inTb + bv.w + c0n + 8);
                }
            }
        }
        cp_wait0();
        __syncthreads();
    }

    // ---- epilogue: stage through smem for coalesced NCHW writes ----
    float* Cs = (float*)smem;   // 64 n x 128 m = 32 KB
    float* ob = out + (size_t)b * COUT * NPIX;
#pragma unroll 1
    for (int nhalf = 0; nhalf < 2; ++nhalf) {
        if (nw == nhalf) {
#pragma unroll
            for (int ma = 0; ma < 2; ++ma)
#pragma unroll
                for (int na = 0; na < 8; ++na)
#pragma unroll
                    for (int d = 0; d < 4; ++d) {
                        int nl = na * 8 + (lane & 3) * 2 + (d & 1);
                        int m = (mw * 2 + ma) * 16 + (lane >> 2) + 8 * (d >> 1);
                        Cs[nl * 128 + m] = acc[ma][na][d];
                    }
        }
        __syncthreads();
#pragma unroll
        for (int it = 0; it < 32; ++it) {
            int idx = tid + it * 256;
            int nl = idx >> 7, m = idx & 127;
            int pp = mtile * MT + m;
            int n = nhalf * 64 + nl;
            if (pp < NPIX)
                ob[(size_t)n * NPIX + pp] = Cs[idx] + bias_s[n];
        }
        __syncthreads();
    }
}

// ---------------------------------------------------------------------------
extern "C" void kernel_launch(void* const* d_in, const int* in_sizes, int n_in,
                              void* d_out, int out_size) {
    const float* inp    = (const float*)d_in[0];
    const float* offset = (const float*)d_in[1];
    const float* mask   = (const float*)d_in[2];
    const float* weight = (const float*)d_in[3];
    const float* bias   = (const float*)d_in[4];
    float* out = (float*)d_out;

    cudaFuncSetAttribute(main_kernel, cudaFuncAttributeMaxDynamicSharedMemorySize,
                         SMEM_TOTAL);

    transpose_kernel<<<BB * HH, 256>>>(inp);
    wpack_kernel<<<(NCHUNK * 2048 + 255) / 256, 256>>>(weight);
    main_kernel<<<dim3(MTILES, BB), 256, SMEM_TOTAL>>>(offset, mask, bias, out);
}